// round 9
// baseline (speedup 1.0000x reference)
#include <cuda_runtime.h>
#include <float.h>
#include <stdint.h>

// Fixed problem shape
#define KC      512         // codebook size
#define DC      64          // code dim
#define HWC     4096        // H*W
#define NC      131072      // B*H*W
#define TPB     512         // 1 pixel per thread, 16 warps
#define TILE    TPB         // 512 pixels per tile
#define NTILES  (NC/TILE)   // 256 tiles
#define GRIDP   128         // 2 tiles per CTA, perfectly balanced
#define KB      16          // codes per k-block -> 8 u64 accums

// smem: even-k-block codebook ETe[64][256] + eNorm[512] + red[512]
#define ETE_FLOATS  (DC * 256)
#define SMEM_FLOATS (ETE_FLOATS + KC + TPB)
#define SMEM_BYTES  (SMEM_FLOATS * 4)

__device__ __align__(16) float g_ET[DC * KC];   // transposed codebook [d][k]
__device__ float    g_part[NTILES];
__device__ unsigned g_done;                     // zero-init; resets each launch

typedef unsigned long long u64;

__device__ __forceinline__ u64 pack2(float x, float y) {
    u64 r;
    asm("mov.b64 %0, {%1, %2};" : "=l"(r) : "f"(x), "f"(y));
    return r;
}
__device__ __forceinline__ void unpack2(u64 v, float& x, float& y) {
    asm("mov.b64 {%0, %1}, %2;" : "=f"(x), "=f"(y) : "l"(v));
}
__device__ __forceinline__ u64 ffma2(u64 a, u64 b, u64 c) {
    u64 d;
    asm("fma.rn.f32x2 %0, %1, %2, %3;" : "=l"(d) : "l"(a), "l"(b), "l"(c));
    return d;
}

__global__ __launch_bounds__(512) void vq_transpose(const float* __restrict__ emb) {
    int idx = blockIdx.x * 512 + threadIdx.x;   // 0..32767
    int k = idx >> 6;
    int d = idx & 63;
    g_ET[d * KC + k] = emb[idx];
}

__global__ __launch_bounds__(TPB, 1)
void vq_kernel(const float* __restrict__ latents,
               const float* __restrict__ embedding,
               float* __restrict__ out,
               float* __restrict__ loss_out) {
    extern __shared__ float smem[];
    float* ETe   = smem;                 // [64][256] even k-blocks, ETe[d*256 + c]
    float* eNorm = smem + ETE_FLOATS;    // [512]
    float* red   = eNorm + KC;           // [512]

    const int tid = threadIdx.x;

    // ---- stage EVEN k-blocks (bi=0,2,..,30 -> k in [32j,32j+16)) into smem ----
    #pragma unroll
    for (int i = tid; i < DC * 256; i += TPB) {
        int d = i >> 8;
        int c = i & 255;
        int j = c >> 4;          // even-block ordinal
        int t = c & 15;
        ETe[i] = g_ET[d * KC + j * 32 + t];
    }

    // ---- enorm_k: sequential d, separate mul/add (XLA reduce emulation) ----
    {
        int k = tid;             // TPB == KC
        float s = 0.0f;
        #pragma unroll
        for (int d = 0; d < DC; ++d) {
            float e = g_ET[d * KC + k];
            s = __fadd_rn(s, __fmul_rn(e, e));
        }
        eNorm[k] = s;
    }
    __syncthreads();

    // ---- persistent tile loop: 2 tiles of 512 pixels per CTA ----
    for (int tile = blockIdx.x; tile < NTILES; tile += GRIDP) {
        const int p  = tile * TILE + tid;
        const int b  = p >> 12;
        const int hw = p & (HWC - 1);
        const float* lat = latents + (size_t)b * DC * HWC + hw;

        float f[DC];
        float fnorm = 0.0f;
        #pragma unroll
        for (int d = 0; d < DC; ++d) {
            f[d] = __ldcs(lat + d * HWC);      // streaming: protect L1 codebook
            fnorm = __fadd_rn(fnorm, __fmul_rn(f[d], f[d]));
        }

        float best  = FLT_MAX;
        int   bestk = 0;

        // ---- argmin over K: alternate even(SMEM)/odd(GMEM/L1) 16-code blocks ----
        #pragma unroll 1
        for (int bj = 0; bj < 16; ++bj) {
            // ===== even block bi=2bj: codes k0e..k0e+15 from SMEM =====
            {
                const int k0 = bj * 32;
                u64 acc[KB / 2];
                #pragma unroll
                for (int j = 0; j < KB / 2; ++j) acc[j] = 0;

                #pragma unroll 8
                for (int d = 0; d < DC; ++d) {
                    const ulonglong2* row =
                        reinterpret_cast<const ulonglong2*>(ETe + d * 256 + bj * 16);
                    const u64 m = pack2(f[d], f[d]);
                    ulonglong2 e01 = row[0];
                    ulonglong2 e23 = row[1];
                    ulonglong2 e45 = row[2];
                    ulonglong2 e67 = row[3];
                    acc[0] = ffma2(m, e01.x, acc[0]);
                    acc[1] = ffma2(m, e01.y, acc[1]);
                    acc[2] = ffma2(m, e23.x, acc[2]);
                    acc[3] = ffma2(m, e23.y, acc[3]);
                    acc[4] = ffma2(m, e45.x, acc[4]);
                    acc[5] = ffma2(m, e45.y, acc[5]);
                    acc[6] = ffma2(m, e67.x, acc[6]);
                    acc[7] = ffma2(m, e67.y, acc[7]);
                }
                #pragma unroll
                for (int j = 0; j < KB / 2; ++j) {
                    int k = k0 + 2 * j;
                    float ax, ay;
                    unpack2(acc[j], ax, ay);
                    float s0 = __fsub_rn(__fadd_rn(fnorm, eNorm[k]),     __fmul_rn(2.0f, ax));
                    float s1 = __fsub_rn(__fadd_rn(fnorm, eNorm[k + 1]), __fmul_rn(2.0f, ay));
                    bestk = (s0 < best) ? k     : bestk;  best = fminf(s0, best);
                    bestk = (s1 < best) ? k + 1 : bestk;  best = fminf(s1, best);
                }
            }
            // ===== odd block bi=2bj+1: codes from transposed GMEM (L1-cached) =====
            {
                const int k0 = bj * 32 + 16;
                u64 acc[KB / 2];
                #pragma unroll
                for (int j = 0; j < KB / 2; ++j) acc[j] = 0;

                #pragma unroll 8
                for (int d = 0; d < DC; ++d) {
                    const ulonglong2* row =
                        reinterpret_cast<const ulonglong2*>(g_ET + d * KC + k0);
                    const u64 m = pack2(f[d], f[d]);
                    ulonglong2 e01 = __ldg(row + 0);
                    ulonglong2 e23 = __ldg(row + 1);
                    ulonglong2 e45 = __ldg(row + 2);
                    ulonglong2 e67 = __ldg(row + 3);
                    acc[0] = ffma2(m, e01.x, acc[0]);
                    acc[1] = ffma2(m, e01.y, acc[1]);
                    acc[2] = ffma2(m, e23.x, acc[2]);
                    acc[3] = ffma2(m, e23.y, acc[3]);
                    acc[4] = ffma2(m, e45.x, acc[4]);
                    acc[5] = ffma2(m, e45.y, acc[5]);
                    acc[6] = ffma2(m, e67.x, acc[6]);
                    acc[7] = ffma2(m, e67.y, acc[7]);
                }
                #pragma unroll
                for (int j = 0; j < KB / 2; ++j) {
                    int k = k0 + 2 * j;
                    float ax, ay;
                    unpack2(acc[j], ax, ay);
                    float s0 = __fsub_rn(__fadd_rn(fnorm, eNorm[k]),     __fmul_rn(2.0f, ax));
                    float s1 = __fsub_rn(__fadd_rn(fnorm, eNorm[k + 1]), __fmul_rn(2.0f, ay));
                    bestk = (s0 < best) ? k     : bestk;  best = fminf(s0, best);
                    bestk = (s1 < best) ? k + 1 : bestk;  best = fminf(s1, best);
                }
            }
        }

        // ---- epilogue: gather code row (original layout), STE output, loss ----
        const float* erow = embedding + (size_t)bestk * DC;
        float* outp = out + (size_t)b * DC * HWC + hw;
        float ldist = 0.0f;
        #pragma unroll
        for (int d = 0; d < DC; ++d) {
            float q  = __ldg(erow + d);
            float dq = __fsub_rn(q, f[d]);               // fl(q - lat)
            ldist = __fadd_rn(ldist, __fmul_rn(dq, dq));
            __stcs(outp + d * HWC, __fadd_rn(f[d], dq)); // fl(lat + (q - lat))
        }

        // ---- per-tile deterministic tree reduce -> g_part[tile] ----
        red[tid] = ldist;
        __syncthreads();
        #pragma unroll
        for (int s = TPB / 2; s > 0; s >>= 1) {
            if (tid < s) red[tid] += red[tid + s];
            __syncthreads();
        }
        if (tid == 0) g_part[tile] = red[0];
        __syncthreads();   // red[] reused next tile
    }

    // ---- grid finalize: last CTA reduces the 256 tile partials ----
    __shared__ unsigned s_last;
    __threadfence();
    if (tid == 0) s_last = (atomicAdd(&g_done, 1u) == GRIDP - 1u);
    __syncthreads();

    if (s_last) {
        red[tid] = (tid < NTILES) ? g_part[tid] : 0.0f;
        __syncthreads();
        #pragma unroll
        for (int s = TPB / 2; s > 0; s >>= 1) {
            if (tid < s) red[tid] += red[tid + s];
            __syncthreads();
        }
        if (tid == 0) {
            float m = red[0] / 8388608.0f;                   // exact /2^23
            *loss_out = __fadd_rn(__fmul_rn(m, 0.25f), m);   // fl(0.25m)+m
            g_done = 0;                                      // reset for replay
        }
    }
}

extern "C" void kernel_launch(void* const* d_in, const int* in_sizes, int n_in,
                              void* d_out, int out_size) {
    const float* latents   = (const float*)d_in[0];   // [32,64,64,64] fp32
    const float* embedding = (const float*)d_in[1];   // [512,64] fp32
    float* out  = (float*)d_out;                      // tensor, then loss scalar
    float* loss = out + (out_size - 1);

    cudaFuncSetAttribute(vq_kernel, cudaFuncAttributeMaxDynamicSharedMemorySize, SMEM_BYTES);

    vq_transpose<<<KC * DC / 512, 512>>>(embedding);
    vq_kernel<<<GRIDP, TPB, SMEM_BYTES>>>(latents, embedding, out, loss);
}

// round 10
// speedup vs baseline: 2.4991x; 2.4991x over previous
#include <cuda_runtime.h>
#include <float.h>
#include <stdint.h>

// Fixed problem shape
#define KC      512         // codebook size
#define DC      64          // code dim
#define HWC     4096        // H*W
#define NC      131072      // B*H*W
#define TPB     256
#define PPT     2           // pixels per thread
#define TILE    (TPB*PPT)   // 512 pixels per tile
#define NTILES  (NC/TILE)   // 256 tiles
#define GRIDP   128         // 2 tiles per CTA, perfectly balanced
#define KB      8           // codes per k-block -> 4 u64 accums per pixel
#define ETS     520         // padded row stride (floats), rows 16B-aligned

// smem floats: ET[64][520] + enorm[512] + red[256]
#define ET_FLOATS   (DC * ETS)
#define SMEM_FLOATS (ET_FLOATS + KC + TPB)
#define SMEM_BYTES  (SMEM_FLOATS * 4)

__device__ float    g_part[NTILES];
__device__ unsigned g_done;         // zero-init; finalizer resets each launch

typedef unsigned long long u64;

__device__ __forceinline__ u64 pack2(float x, float y) {
    u64 r;
    asm("mov.b64 %0, {%1, %2};" : "=l"(r) : "f"(x), "f"(y));
    return r;
}
__device__ __forceinline__ void unpack2(u64 v, float& x, float& y) {
    asm("mov.b64 {%0, %1}, %2;" : "=f"(x), "=f"(y) : "l"(v));
}
__device__ __forceinline__ u64 ffma2(u64 a, u64 b, u64 c) {
    u64 d;
    asm("fma.rn.f32x2 %0, %1, %2, %3;" : "=l"(d) : "l"(a), "l"(b), "l"(c));
    return d;
}

__global__ __launch_bounds__(TPB, 1)
void vq_kernel(const float* __restrict__ latents,
               const float* __restrict__ embedding,
               float* __restrict__ out,
               float* __restrict__ loss_out) {
    extern __shared__ float smem[];
    float* ET    = smem;                 // [64][520], ET[d*ETS + k]
    float* eNorm = smem + ET_FLOATS;     // [512]
    float* red   = eNorm + KC;           // [256]

    const int tid = threadIdx.x;

    // ---- stage transposed codebook once per CTA ----
    {
        const float4* src = reinterpret_cast<const float4*>(embedding);
        #pragma unroll
        for (int i4 = tid; i4 < (KC * DC) / 4; i4 += TPB) {
            float4 v = src[i4];
            int i = i4 * 4;
            int k = i >> 6;
            int d = i & 63;
            ET[(d + 0) * ETS + k] = v.x;
            ET[(d + 1) * ETS + k] = v.y;
            ET[(d + 2) * ETS + k] = v.z;
            ET[(d + 3) * ETS + k] = v.w;
        }
    }
    __syncthreads();

    // ---- enorm_k: sequential d, separate mul/add (XLA reduce emulation) ----
    #pragma unroll
    for (int k = tid; k < KC; k += TPB) {
        float s = 0.0f;
        #pragma unroll
        for (int d = 0; d < DC; ++d) {
            float e = ET[d * ETS + k];
            s = __fadd_rn(s, __fmul_rn(e, e));
        }
        eNorm[k] = s;
    }
    __syncthreads();

    // ---- persistent tile loop: 2 tiles of 512 pixels per CTA ----
    for (int tile = blockIdx.x; tile < NTILES; tile += GRIDP) {
        const int pA = tile * TILE + tid;        // pixel A
        const int pB = pA + TPB;                 // pixel B
        const int bA = pA >> 12, hwA = pA & (HWC - 1);
        const int bB = pB >> 12, hwB = pB & (HWC - 1);
        const float* latA = latents + (size_t)bA * DC * HWC + hwA;
        const float* latB = latents + (size_t)bB * DC * HWC + hwB;

        float fA[DC], fB[DC];
        float fnA = 0.0f, fnB = 0.0f;
        #pragma unroll
        for (int d = 0; d < DC; ++d) {
            fA[d] = latA[d * HWC];
            fB[d] = latB[d * HWC];
            fnA = __fadd_rn(fnA, __fmul_rn(fA[d], fA[d]));
            fnB = __fadd_rn(fnB, __fmul_rn(fB[d], fB[d]));
        }

        float bestA = FLT_MAX, bestB = FLT_MAX;
        int   bkA = 0, bkB = 0;

        // ---- argmin over K: 8 codes per k-block, both pixels share e-loads ----
        #pragma unroll 1
        for (int k0 = 0; k0 < KC; k0 += KB) {
            u64 aA0 = 0, aA1 = 0, aA2 = 0, aA3 = 0;
            u64 aB0 = 0, aB1 = 0, aB2 = 0, aB3 = 0;

            #pragma unroll
            for (int d = 0; d < DC; ++d) {
                const ulonglong2* row =
                    reinterpret_cast<const ulonglong2*>(ET + d * ETS + k0);
                ulonglong2 e01 = row[0];       // codes k0..k0+3
                ulonglong2 e23 = row[1];       // codes k0+4..k0+7
                const u64 mA = pack2(fA[d], fA[d]);
                const u64 mB = pack2(fB[d], fB[d]);
                aA0 = ffma2(mA, e01.x, aA0);   aB0 = ffma2(mB, e01.x, aB0);
                aA1 = ffma2(mA, e01.y, aA1);   aB1 = ffma2(mB, e01.y, aB1);
                aA2 = ffma2(mA, e23.x, aA2);   aB2 = ffma2(mB, e23.x, aB2);
                aA3 = ffma2(mA, e23.y, aA3);   aB3 = ffma2(mB, e23.y, aB3);
            }

            // score (ascending k => first-min preserved)
            u64 accA[4] = {aA0, aA1, aA2, aA3};
            u64 accB[4] = {aB0, aB1, aB2, aB3};
            #pragma unroll
            for (int j = 0; j < 4; ++j) {
                int k = k0 + 2 * j;
                float en0 = eNorm[k];
                float en1 = eNorm[k + 1];
                float aAx, aAy, aBx, aBy;
                unpack2(accA[j], aAx, aAy);
                unpack2(accB[j], aBx, aBy);
                float sA0 = __fsub_rn(__fadd_rn(fnA, en0), __fmul_rn(2.0f, aAx));
                float sA1 = __fsub_rn(__fadd_rn(fnA, en1), __fmul_rn(2.0f, aAy));
                float sB0 = __fsub_rn(__fadd_rn(fnB, en0), __fmul_rn(2.0f, aBx));
                float sB1 = __fsub_rn(__fadd_rn(fnB, en1), __fmul_rn(2.0f, aBy));
                bkA = (sA0 < bestA) ? k     : bkA;  bestA = fminf(sA0, bestA);
                bkA = (sA1 < bestA) ? k + 1 : bkA;  bestA = fminf(sA1, bestA);
                bkB = (sB0 < bestB) ? k     : bkB;  bestB = fminf(sB0, bestB);
                bkB = (sB1 < bestB) ? k + 1 : bkB;  bestB = fminf(sB1, bestB);
            }
        }

        // ---- epilogue: gather codes, STE outputs, per-pixel loss partials ----
        float* outA = out + (size_t)bA * DC * HWC + hwA;
        float* outB = out + (size_t)bB * DC * HWC + hwB;
        float ldist = 0.0f;
        #pragma unroll
        for (int d = 0; d < DC; ++d) {
            float qA = ET[d * ETS + bkA];
            float qB = ET[d * ETS + bkB];
            float dqA = __fsub_rn(qA, fA[d]);
            float dqB = __fsub_rn(qB, fB[d]);
            ldist = __fadd_rn(ldist, __fmul_rn(dqA, dqA));
            ldist = __fadd_rn(ldist, __fmul_rn(dqB, dqB));
            outA[d * HWC] = __fadd_rn(fA[d], dqA);
            outB[d * HWC] = __fadd_rn(fB[d], dqB);
        }

        // ---- per-tile deterministic tree reduce -> g_part[tile] ----
        red[tid] = ldist;
        __syncthreads();
        #pragma unroll
        for (int s = TPB / 2; s > 0; s >>= 1) {
            if (tid < s) red[tid] += red[tid + s];
            __syncthreads();
        }
        if (tid == 0) g_part[tile] = red[0];
        __syncthreads();   // red[] reused next tile
    }

    // ---- grid finalize: last CTA reduces the 256 tile partials ----
    __shared__ unsigned s_last;
    __threadfence();
    if (tid == 0) s_last = (atomicAdd(&g_done, 1u) == GRIDP - 1u);
    __syncthreads();

    if (s_last) {
        red[tid] = g_part[tid];
        __syncthreads();
        #pragma unroll
        for (int s = TPB / 2; s > 0; s >>= 1) {
            if (tid < s) red[tid] += red[tid + s];
            __syncthreads();
        }
        if (tid == 0) {
            float m = red[0] / 8388608.0f;                   // exact /2^23
            *loss_out = __fadd_rn(__fmul_rn(m, 0.25f), m);   // fl(0.25m)+m
            g_done = 0;                                      // reset for replay
        }
    }
}

extern "C" void kernel_launch(void* const* d_in, const int* in_sizes, int n_in,
                              void* d_out, int out_size) {
    const float* latents   = (const float*)d_in[0];   // [32,64,64,64] fp32
    const float* embedding = (const float*)d_in[1];   // [512,64] fp32
    float* out  = (float*)d_out;                      // tensor, then loss scalar
    float* loss = out + (out_size - 1);

    cudaFuncSetAttribute(vq_kernel, cudaFuncAttributeMaxDynamicSharedMemorySize, SMEM_BYTES);
    vq_kernel<<<GRIDP, TPB, SMEM_BYTES>>>(latents, embedding, out, loss);
}